// round 10
// baseline (speedup 1.0000x reference)
#include <cuda_runtime.h>

#define NEGV (-1e30f)

__device__ __forceinline__ float4 fmax4(float4 a, float4 b) {
    a.x = fmaxf(a.x, b.x);
    a.y = fmaxf(a.y, b.y);
    a.z = fmaxf(a.z, b.z);
    a.w = fmaxf(a.w, b.w);
    return a;
}

// Persistent balanced warp-task kernel.
// Warp-task t = (token, side, half):
//   side: 0 = left path, 1 = right path
//   half: 0 = d[0:128),  1 = d[128:256)
// Grid = one resident wave (16 blocks/SM at 32 regs); each warp strides over
// tasks so per-warp work averages out (masked tokens cost ~10 instructions
// and the warp moves on instead of retiring its block slot).
// Inner loop: lane p holds paths[token][p] (P == 32); index broadcast is a
// shfl on register state only, so unroll-4 keeps 4 gather LDG.128 in flight.
__global__ __launch_bounds__(128, 16) void path_max_kernel(
    const float* __restrict__ inputs,   // [B,L,D] f32, D=256
    const int*   __restrict__ lpaths,   // [B,L,P]
    const int*   __restrict__ rpaths,   // [B,L,P]
    const int*   __restrict__ llens,    // [B,L]
    const int*   __restrict__ rlens,    // [B,L]
    const int*   __restrict__ slens,    // [B]
    float*       __restrict__ out,      // [B,L,2D]
    int ntasks)                         // B * L * 4
{
    constexpr int L = 512, P = 32;

    const int lane = threadIdx.x & 31;
    const int W    = gridDim.x << 2;                       // total warps
    const int w0   = (blockIdx.x << 2) + (threadIdx.x >> 5);

    for (int t = w0; t < ntasks; t += W) {
        const int token = t >> 2;
        const int side  = (t >> 1) & 1;
        const int half  = t & 1;
        const int b     = token >> 9;        // token / L
        const int l     = token & (L - 1);   // token % L

        // Token row has 512 floats = 128 float4; this task owns 32 of them.
        float4* o4 = reinterpret_cast<float4*>(out)
                   + (size_t)token * 128 + side * 64 + half * 32 + lane;

        if (l >= __ldg(&slens[b])) {
            *o4 = make_float4(0.f, 0.f, 0.f, 0.f);
            continue;
        }

        const int* __restrict__ paths = side ? rpaths : lpaths;
        const int len = side ? __ldg(&rlens[token]) : __ldg(&llens[token]);
        const int my  = __ldg(&paths[(size_t)token * P + lane]);

        // Each row of inputs[b] is 64 float4; this task reads float4 column
        // (half*32 + lane) of each gathered row -> coalesced 512B LDG.128.
        const float4* __restrict__ base =
            reinterpret_cast<const float4*>(inputs)
            + (size_t)b * L * 64 + half * 32 + lane;

        float4 m = make_float4(NEGV, NEGV, NEGV, NEGV);

        int idx = __shfl_sync(0xffffffffu, my, 0);
        #pragma unroll 4
        for (int p = 0; p < len; ++p) {
            const float4 v = __ldg(base + (size_t)idx * 64);
            idx = __shfl_sync(0xffffffffu, my, (p + 1) & 31);  // indep. of v
            m = fmax4(m, v);
        }

        *o4 = m;
    }
}

extern "C" void kernel_launch(void* const* d_in, const int* in_sizes, int n_in,
                              void* d_out, int out_size) {
    const float* inputs = (const float*)d_in[0];
    const int*   lpaths = (const int*)d_in[1];
    const int*   rpaths = (const int*)d_in[2];
    const int*   llens  = (const int*)d_in[3];
    const int*   rlens  = (const int*)d_in[4];
    const int*   slens  = (const int*)d_in[5];

    const int B = in_sizes[5];          // sent_lens has B elements
    const int ntasks = B * 512 * 4;     // (token, side, half) warp-tasks

    // One resident wave: 16 blocks/SM x 148 SMs (regs capped at 32).
    int blocks = 148 * 16;
    const int max_blocks = (ntasks + 3) / 4;   // at least 1 task per warp
    if (blocks > max_blocks) blocks = max_blocks;

    path_max_kernel<<<blocks, 128>>>(inputs, lpaths, rpaths,
                                     llens, rlens, slens,
                                     (float*)d_out, ntasks);
}

// round 11
// speedup vs baseline: 1.4098x; 1.4098x over previous
#include <cuda_runtime.h>

#define NEGV (-1e30f)

__device__ __forceinline__ float4 fmax4(float4 a, float4 b) {
    a.x = fmaxf(a.x, b.x);
    a.y = fmaxf(a.y, b.y);
    a.z = fmaxf(a.z, b.z);
    a.w = fmaxf(a.w, b.w);
    return a;
}

// One block (64 threads = 2 warps) per (token, side):
//   warp 0: d[  0:128)
//   warp 1: d[128:256)
// Finest CTA granularity that keeps full occupancy (32 blocks/SM x 2 warps
// = 64 warps/SM at 32 regs): a block pins at most 1 idle warp behind a long
// path, masked blocks free both slots instantly, and left/right path-length
// imbalance no longer couples inside one CTA.
// Lane p holds paths[token][p] (P == 32); index broadcast is a shfl on
// register state only, so unroll-4 keeps ~4 gather LDG.128 in flight.
__global__ __launch_bounds__(64, 32) void path_max_kernel(
    const float* __restrict__ inputs,   // [B,L,D] f32, D=256
    const int*   __restrict__ lpaths,   // [B,L,P]
    const int*   __restrict__ rpaths,   // [B,L,P]
    const int*   __restrict__ llens,    // [B,L]
    const int*   __restrict__ rlens,    // [B,L]
    const int*   __restrict__ slens,    // [B]
    float*       __restrict__ out)      // [B,L,2D]
{
    constexpr int L = 512, P = 32;

    const int token = blockIdx.x >> 1;
    const int side  = blockIdx.x & 1;    // 0 = left, 1 = right
    const int half  = threadIdx.x >> 5;  // 0 = d[0:128), 1 = d[128:256)
    const int lane  = threadIdx.x & 31;
    const int b     = token >> 9;        // token / L
    const int l     = token & (L - 1);   // token % L

    // Token row has 512 floats = 128 float4; this warp owns 32 of them.
    float4* o4 = reinterpret_cast<float4*>(out)
               + (size_t)token * 128 + side * 64 + half * 32 + lane;

    if (l >= __ldg(&slens[b])) {
        *o4 = make_float4(0.f, 0.f, 0.f, 0.f);
        return;
    }

    const int* __restrict__ paths = side ? rpaths : lpaths;
    const int len = side ? __ldg(&rlens[token]) : __ldg(&llens[token]);
    const int my  = __ldg(&paths[(size_t)token * P + lane]);

    // Each row of inputs[b] is 64 float4; this warp reads float4 column
    // (half*32 + lane) of each gathered row -> coalesced 512B per LDG.128.
    const float4* __restrict__ base =
        reinterpret_cast<const float4*>(inputs)
        + (size_t)b * L * 64 + half * 32 + lane;

    float4 m = make_float4(NEGV, NEGV, NEGV, NEGV);

    int idx = __shfl_sync(0xffffffffu, my, 0);
    #pragma unroll 4
    for (int p = 0; p < len; ++p) {
        const float4 v = __ldg(base + (size_t)idx * 64);
        idx = __shfl_sync(0xffffffffu, my, (p + 1) & 31);  // independent of v
        m = fmax4(m, v);
    }

    *o4 = m;
}

extern "C" void kernel_launch(void* const* d_in, const int* in_sizes, int n_in,
                              void* d_out, int out_size) {
    const float* inputs = (const float*)d_in[0];
    const int*   lpaths = (const int*)d_in[1];
    const int*   rpaths = (const int*)d_in[2];
    const int*   llens  = (const int*)d_in[3];
    const int*   rlens  = (const int*)d_in[4];
    const int*   slens  = (const int*)d_in[5];

    const int B = in_sizes[5];          // sent_lens has B elements
    const int blocks = B * 512 * 2;     // one block per (token, side)

    path_max_kernel<<<blocks, 64>>>(inputs, lpaths, rpaths,
                                    llens, rlens, slens,
                                    (float*)d_out);
}